// round 11
// baseline (speedup 1.0000x reference)
#include <cuda_runtime.h>
#include <cstdint>
#include <math.h>

// CTC forward loss, linear domain, one warp per batch element, PER-LANE scaling.
// Lane l owns lattice positions s=8l..8l+7 (+shadow s=8l+8 in a256; real on
// lane 31). Cross-lane dep: one __shfl_up of a7 per step, rescaled by
// sF = 2^(E_prev - E) (exact power of two; 0 on lane 0).
// Every 4 steps per lane: band-zero (exact reachability pruning), renormalize
// to the lane-local max by an exact power of two (int exponent E), adopt the
// left neighbor's E when the lane is all-zero (activation frontier moves one
// lane per 4 steps). Emissions: cp.async 4-deep shared ring of log-prob rows;
// 5 gathers + 5 __expf per step.

constexpr int N_ = 512;
constexpr int C_ = 80;
constexpr int S_ = 128;
constexpr int T_ = 512;
constexpr int NC = N_ * C_;
constexpr int WPB  = 4;
constexpr int ROWW = 96;
constexpr int RING = 4;
constexpr int WSLOT = ROWW * RING;

__device__ __forceinline__ void cp16(unsigned int dst, const float* src) {
    asm volatile("cp.async.ca.shared.global [%0], [%1], 16;" :: "r"(dst), "l"(src));
}
__device__ __forceinline__ void cpcommit() { asm volatile("cp.async.commit_group;"); }
__device__ __forceinline__ void cpwait2()  { asm volatile("cp.async.wait_group 2;" ::: "memory"); }
__device__ __forceinline__ void cpwait0()  { asm volatile("cp.async.wait_group 0;" ::: "memory"); }

__global__ __launch_bounds__(WPB * 32)
void ctc_kernel(const float* __restrict__ lp, const int* __restrict__ tgt,
                const int* __restrict__ ilen, const int* __restrict__ tlen,
                float* __restrict__ out)
{
    __shared__ __align__(16) float buf[WPB][WSLOT];
    __shared__ float aval[WPB][260];
    __shared__ int   epos[WPB][32];

    const int lane = threadIdx.x & 31;
    const int w    = threadIdx.x >> 5;
    const int n    = blockIdx.x * WPB + w;
    const int len  = ilen[n];            // [T/2, T]
    const int tl   = tlen[n];            // [S/2, S]
    const int hi   = 2 * tl;             // readout states hi, hi-1

    const int4 lab4 = *reinterpret_cast<const int4*>(tgt + n * S_ + 4 * lane);
    const int l0 = lab4.x, l1 = lab4.y, l2 = lab4.z, l3 = lab4.w;
    const int prevlab = __shfl_up_sync(0xffffffffu, l3, 1);
    const float sk0 = (lane > 0 && l0 != prevlab) ? 1.f : 0.f;
    const float sk1 = (l1 != l0) ? 1.f : 0.f;
    const float sk2 = (l2 != l1) ? 1.f : 0.f;
    const float sk3 = (l3 != l2) ? 1.f : 0.f;

    const float* gsrc = lp + (size_t)n * C_ + 4 * lane;
    const unsigned int sbase = (unsigned int)__cvta_generic_to_shared(&buf[w][0]);

    #pragma unroll
    for (int r = 0; r < RING; ++r) {
        if (lane < 20) cp16(sbase + r * (ROWW * 4) + lane * 16, gsrc + (size_t)r * NC);
        cpcommit();
    }
    cpwait0();
    __syncwarp();

    float a0 = 0, a1 = 0, a2 = 0, a3 = 0, a4 = 0, a5 = 0, a6 = 0, a7 = 0, a256 = 0;
    {
        const float i0 = buf[w][0];
        const float i1 = buf[w][l0];
        if (lane == 0) { a0 = __expf(i0); a1 = __expf(i1); }
    }
    const float* r1 = &buf[w][ROWW];
    float egb = __expf(r1[0]);
    float eg0 = __expf(r1[l0]), eg1 = __expf(r1[l1]);
    float eg2 = __expf(r1[l2]), eg3 = __expf(r1[l3]);

    int   E  = 0;                         // per-lane exponent
    float sF = (lane == 0) ? 0.f : 1.f;   // 2^(E_prev - E), 0 on lane 0
    const int ibase = lane << 3;

    for (int t = 1; t < len; ++t) {
        const float pa7 = __shfl_up_sync(0xffffffffu, a7, 1) * sF;

        const float n0 = (a0 + pa7) * egb;
        const float n1 = (a1 + a0 + sk0 * pa7) * eg0;
        const float n2 = (a2 + a1) * egb;
        const float n3 = (a3 + a2 + sk1 * a1) * eg1;
        const float n4 = (a4 + a3) * egb;
        const float n5 = (a5 + a4 + sk2 * a3) * eg2;
        const float n6 = (a6 + a5) * egb;
        const float n7 = (a7 + a6 + sk3 * a5) * eg3;
        a256 = (a256 + a7) * egb;
        a0 = n0; a1 = n1; a2 = n2; a3 = n3;
        a4 = n4; a5 = n5; a6 = n6; a7 = n7;

        if ((t & 3) == 0) {
            // Exact reachability band-zero: keep lo <= s <= hi.
            const int lo = hi - 1 - 2 * (len - 1 - t);
            const int il = lo - ibase;
            const int ih = hi - ibase;
            a0   = (0 >= il && 0 <= ih) ? a0   : 0.f;
            a1   = (1 >= il && 1 <= ih) ? a1   : 0.f;
            a2   = (2 >= il && 2 <= ih) ? a2   : 0.f;
            a3   = (3 >= il && 3 <= ih) ? a3   : 0.f;
            a4   = (4 >= il && 4 <= ih) ? a4   : 0.f;
            a5   = (5 >= il && 5 <= ih) ? a5   : 0.f;
            a6   = (6 >= il && 6 <= ih) ? a6   : 0.f;
            a7   = (7 >= il && 7 <= ih) ? a7   : 0.f;
            a256 = (8 >= il && 8 <= ih) ? a256 : 0.f;

            // Lane-local renormalization by an exact power of two.
            float m = fmaxf(fmaxf(fmaxf(a0, a1), fmaxf(a2, a3)),
                            fmaxf(fmaxf(a4, a5), fmaxf(a6, a7)));
            m = fmaxf(m, a256);
            const bool nz = (m > 0.f);
            if (nz) {
                const int eb = (__float_as_int(m) >> 23) - 127;
                const float sc = __int_as_float((254 - (127 + eb)) << 23); // 2^-eb
                E += eb;
                a0 *= sc; a1 *= sc; a2 *= sc; a3 *= sc;
                a4 *= sc; a5 *= sc; a6 *= sc; a7 *= sc; a256 *= sc;
            }
            // Neighbor exponent exchange; adopt when lane is empty (frontier).
            const int Eprev = __shfl_up_sync(0xffffffffu, E, 1);
            if (!nz) E = Eprev;
            int dE = Eprev - E;
            dE = max(-126, min(126, dE));
            sF = (lane == 0) ? 0.f : __int_as_float((127 + dE) << 23);
        }

        // Prefetch log row t+3 into the slot of dead row t-1.
        {
            const int rnext = min(t + 3, T_ - 1);
            if (lane < 20)
                cp16(sbase + ((t + 3) & 3) * (ROWW * 4) + lane * 16,
                     gsrc + (size_t)rnext * NC);
            cpcommit();
            cpwait2();
            __syncwarp();
        }
        const float* rr = &buf[w][((t + 1) & 3) * ROWW];
        egb = __expf(rr[0]);
        eg0 = __expf(rr[l0]); eg1 = __expf(rr[l1]);
        eg2 = __expf(rr[l2]); eg3 = __expf(rr[l3]);
    }

    // Readout: alpha_true[s] = aval[s] * 2^E(lane(s)).
    aval[w][ibase + 0] = a0; aval[w][ibase + 1] = a1;
    aval[w][ibase + 2] = a2; aval[w][ibase + 3] = a3;
    aval[w][ibase + 4] = a4; aval[w][ibase + 5] = a5;
    aval[w][ibase + 6] = a6; aval[w][ibase + 7] = a7;
    epos[w][lane] = E;
    if (lane == 31) aval[w][256] = a256;
    __syncwarp();
    if (lane == 0) {
        const float v1 = aval[w][hi];
        const float v2 = aval[w][hi - 1];
        int E1 = epos[w][min(hi >> 3, 31)];
        int E2 = epos[w][(hi - 1) >> 3];
        E1 = (v1 > 0.f) ? E1 : -2000000;   // ignore exponent of zero terms
        E2 = (v2 > 0.f) ? E2 : -2000000;
        const int Em = max(E1, E2);
        const double sum = ldexp((double)v1, max(E1 - Em, -1000))
                         + ldexp((double)v2, max(E2 - Em, -1000));
        const double loss = -((double)Em * 0.6931471805599453 + log(sum));
        float lf = (float)loss;
        if (!isfinite(lf) || !(lf < 1e10f)) lf = 0.f;   // zero_infinity
        out[n] = lf;
    }
}

extern "C" void kernel_launch(void* const* d_in, const int* in_sizes, int n_in,
                              void* d_out, int out_size)
{
    const float* lp   = (const float*)d_in[0];
    const int*   tgt  = (const int*)  d_in[1];
    const int*   ilen = (const int*)  d_in[2];
    const int*   tlen = (const int*)  d_in[3];
    float*       out  = (float*)      d_out;

    ctc_kernel<<<N_ / WPB, WPB * 32>>>(lp, tgt, ilen, tlen, out);
}

// round 12
// speedup vs baseline: 1.2848x; 1.2848x over previous
#include <cuda_runtime.h>
#include <cstdint>
#include <math.h>

// CTC forward loss, linear domain, one warp per batch element, per-lane
// power-of-two scaling. Lane l owns s=8l..8l+7 (+shadow s=8l+8 in a256).
// R12: 4-step blocks. Emissions for block k+1 are gathered+exp'd into
// registers during block k, so the 4 alpha steps touch no smem (chain =
// shfl + FADD/FMUL only). One cp.async group (4 rows) per block, 16-row
// ring, issued 4 blocks ahead; one wait_group+syncwarp per block.

constexpr int N_ = 512;
constexpr int C_ = 80;
constexpr int S_ = 128;
constexpr int T_ = 512;
constexpr int NC = N_ * C_;
constexpr int WPB  = 4;
constexpr int ROWW = 96;          // floats per ring row (row data = 80)
constexpr int RING = 16;          // rows in ring
constexpr int WSLOT = ROWW * RING;

__device__ __forceinline__ void cp16(unsigned int dst, const float* src) {
    asm volatile("cp.async.ca.shared.global [%0], [%1], 16;" :: "r"(dst), "l"(src));
}
__device__ __forceinline__ void cpcommit() { asm volatile("cp.async.commit_group;"); }
__device__ __forceinline__ void cpwait1()  { asm volatile("cp.async.wait_group 1;" ::: "memory"); }

__global__ __launch_bounds__(WPB * 32)
void ctc_kernel(const float* __restrict__ lp, const int* __restrict__ tgt,
                const int* __restrict__ ilen, const int* __restrict__ tlen,
                float* __restrict__ out)
{
    __shared__ __align__(16) float buf[WPB][WSLOT];
    __shared__ float aval[WPB][260];
    __shared__ int   epos[WPB][32];

    const int lane = threadIdx.x & 31;
    const int w    = threadIdx.x >> 5;
    const int n    = blockIdx.x * WPB + w;
    const int len  = ilen[n];            // [T/2, T]
    const int tl   = tlen[n];            // [S/2, S]
    const int hi   = 2 * tl;             // readout states hi, hi-1

    const int4 lab4 = *reinterpret_cast<const int4*>(tgt + n * S_ + 4 * lane);
    const int l0 = lab4.x, l1 = lab4.y, l2 = lab4.z, l3 = lab4.w;
    const int prevlab = __shfl_up_sync(0xffffffffu, l3, 1);
    const float sk0 = (lane > 0 && l0 != prevlab) ? 1.f : 0.f;
    const float sk1 = (l1 != l0) ? 1.f : 0.f;
    const float sk2 = (l2 != l1) ? 1.f : 0.f;
    const float sk3 = (l3 != l2) ? 1.f : 0.f;

    const float* gsrc = lp + (size_t)n * C_ + 4 * lane;
    const unsigned int sbase = (unsigned int)__cvta_generic_to_shared(&buf[w][0]);

    // Issue one cp.async commit-group per 4-row group g (nominal rows 4g..4g+3,
    // source row clamped to T-1, ring slot by nominal row & 15).
    auto issue_group = [&](int g) {
        if (lane < 20) {
            const int r0 = 4 * g;
            #pragma unroll
            for (int j = 0; j < 4; ++j) {
                const int rn = r0 + j;
                cp16(sbase + ((rn & (RING - 1)) * ROWW + 4 * lane) * 4,
                     gsrc + (size_t)min(rn, T_ - 1) * NC);
            }
        }
        cpcommit();
    };

    // Prologue: groups 0..3 in flight; wait so groups 0..2 are complete.
    issue_group(0); issue_group(1); issue_group(2); issue_group(3);
    cpwait1();
    __syncwarp();

    // alpha(0) from row 0.
    float a0 = 0, a1 = 0, a2 = 0, a3 = 0, a4 = 0, a5 = 0, a6 = 0, a7 = 0, a256 = 0;
    if (lane == 0) { a0 = __expf(buf[w][0]); a1 = __expf(buf[w][l0]); }

    // Emission registers for the upcoming 4 steps (j = step within block).
    float egb[4], eg0[4], eg1[4], eg2[4], eg3[4];
    #pragma unroll
    for (int j = 0; j < 4; ++j) {          // rows 1..4 (groups 0,1: complete)
        const float* rr = &buf[w][((1 + j) & (RING - 1)) * ROWW];
        egb[j] = __expf(rr[0]);
        eg0[j] = __expf(rr[l0]); eg1[j] = __expf(rr[l1]);
        eg2[j] = __expf(rr[l2]); eg3[j] = __expf(rr[l3]);
    }

    int   E  = 0;
    float sF = (lane == 0) ? 0.f : 1.f;    // 2^(E_prev - E); 0 on lane 0
    const int ibase = lane << 3;

    // One alpha step using emission set j (registers only).
    #define ASTEP(j)                                                        \
    {                                                                       \
        const float pa7 = __shfl_up_sync(0xffffffffu, a7, 1) * sF;          \
        const float n0 = (a0 + pa7) * egb[j];                               \
        const float n1 = (a1 + a0 + sk0 * pa7) * eg0[j];                    \
        const float n2 = (a2 + a1) * egb[j];                                \
        const float n3 = (a3 + a2 + sk1 * a1) * eg1[j];                     \
        const float n4 = (a4 + a3) * egb[j];                                \
        const float n5 = (a5 + a4 + sk2 * a3) * eg2[j];                     \
        const float n6 = (a6 + a5) * egb[j];                                \
        const float n7 = (a7 + a6 + sk3 * a5) * eg3[j];                     \
        a256 = (a256 + a7) * egb[j];                                        \
        a0 = n0; a1 = n1; a2 = n2; a3 = n3;                                 \
        a4 = n4; a5 = n5; a6 = n6; a7 = n7;                                 \
    }

    const int kmax = (len - 5) >> 2;       // blocks k=0..kmax, t = 4k+1..4k+4
    for (int k = 0; k <= kmax; ++k) {
        ASTEP(0); ASTEP(1); ASTEP(2); ASTEP(3);

        // Band-zero (exact reachability, at t = 4k+4) + per-lane renorm.
        {
            const int t  = 4 * k + 4;
            const int lo = hi - 1 - 2 * (len - 1 - t);
            const int il = lo - ibase;
            const int ih = hi - ibase;
            a0   = (0 >= il && 0 <= ih) ? a0   : 0.f;
            a1   = (1 >= il && 1 <= ih) ? a1   : 0.f;
            a2   = (2 >= il && 2 <= ih) ? a2   : 0.f;
            a3   = (3 >= il && 3 <= ih) ? a3   : 0.f;
            a4   = (4 >= il && 4 <= ih) ? a4   : 0.f;
            a5   = (5 >= il && 5 <= ih) ? a5   : 0.f;
            a6   = (6 >= il && 6 <= ih) ? a6   : 0.f;
            a7   = (7 >= il && 7 <= ih) ? a7   : 0.f;
            a256 = (8 >= il && 8 <= ih) ? a256 : 0.f;

            float m = fmaxf(fmaxf(fmaxf(a0, a1), fmaxf(a2, a3)),
                            fmaxf(fmaxf(a4, a5), fmaxf(a6, a7)));
            m = fmaxf(m, a256);
            const bool nz = (m > 0.f);
            if (nz) {
                const int eb = (__float_as_int(m) >> 23) - 127;
                const float sc = __int_as_float((127 - eb) << 23);  // 2^-eb
                E += eb;
                a0 *= sc; a1 *= sc; a2 *= sc; a3 *= sc;
                a4 *= sc; a5 *= sc; a6 *= sc; a7 *= sc; a256 *= sc;
            }
            const int Eprev = __shfl_up_sync(0xffffffffu, E, 1);
            if (!nz) E = Eprev;
            int dE = Eprev - E;
            dE = max(-126, min(126, dE));
            sF = (lane == 0) ? 0.f : __int_as_float((127 + dE) << 23);
        }

        // Keep 4 groups in flight; ensure groups <= k+3 complete, then
        // gather+exp emissions for block k+1 (rows 4k+5..4k+8; groups k+1,k+2).
        issue_group(k + 4);
        cpwait1();
        __syncwarp();
        #pragma unroll
        for (int j = 0; j < 4; ++j) {
            const float* rr = &buf[w][((4 * k + 5 + j) & (RING - 1)) * ROWW];
            egb[j] = __expf(rr[0]);
            eg0[j] = __expf(rr[l0]); eg1[j] = __expf(rr[l1]);
            eg2[j] = __expf(rr[l2]); eg3[j] = __expf(rr[l3]);
        }
    }

    // Tail: t = 4*(kmax+1)+1 .. len-1 (0..3 steps) using prefetched egs.
    {
        const int t0 = 4 * (kmax + 1) + 1;
        if (t0 + 0 < len) ASTEP(0);
        if (t0 + 1 < len) ASTEP(1);
        if (t0 + 2 < len) ASTEP(2);
    }
    #undef ASTEP

    // Readout: alpha_true[s] = aval[s] * 2^E(lane(s)).
    aval[w][ibase + 0] = a0; aval[w][ibase + 1] = a1;
    aval[w][ibase + 2] = a2; aval[w][ibase + 3] = a3;
    aval[w][ibase + 4] = a4; aval[w][ibase + 5] = a5;
    aval[w][ibase + 6] = a6; aval[w][ibase + 7] = a7;
    epos[w][lane] = E;
    if (lane == 31) aval[w][256] = a256;
    __syncwarp();
    if (lane == 0) {
        const float v1 = aval[w][hi];
        const float v2 = aval[w][hi - 1];
        int E1 = epos[w][min(hi >> 3, 31)];
        int E2 = epos[w][(hi - 1) >> 3];
        E1 = (v1 > 0.f) ? E1 : -2000000;
        E2 = (v2 > 0.f) ? E2 : -2000000;
        const int Em = max(E1, E2);
        const double sum = ldexp((double)v1, max(E1 - Em, -1000))
                         + ldexp((double)v2, max(E2 - Em, -1000));
        const double loss = -((double)Em * 0.6931471805599453 + log(sum));
        float lf = (float)loss;
        if (!isfinite(lf) || !(lf < 1e10f)) lf = 0.f;   // zero_infinity
        out[n] = lf;
    }
}

extern "C" void kernel_launch(void* const* d_in, const int* in_sizes, int n_in,
                              void* d_out, int out_size)
{
    const float* lp   = (const float*)d_in[0];
    const int*   tgt  = (const int*)  d_in[1];
    const int*   ilen = (const int*)  d_in[2];
    const int*   tlen = (const int*)  d_in[3];
    float*       out  = (float*)      d_out;

    ctc_kernel<<<N_ / WPB, WPB * 32>>>(lp, tgt, ilen, tlen, out);
}

// round 14
// speedup vs baseline: 2.3820x; 1.8539x over previous
#include <cuda_runtime.h>
#include <cstdint>
#include <math.h>

// CTC forward loss, linear domain, one warp per batch element, per-lane
// power-of-two scaling. Lane l owns s=8l..8l+7 (+shadow s=8l+8 in a256).
// R13: deep cp.async pipeline. 32-row ring (8 groups of 4 rows); block k
// issues group k+8 and waits with wait_group 5 => groups <= k+3 complete,
// 5-block (~750+ cyc) lead over the gather that needs groups <= k+2.
// Emissions for block k+1 gathered+exp'd into registers during block k, so
// the 4 alpha steps are shfl+FADD/FFMA/FMUL only.

constexpr int N_ = 512;
constexpr int C_ = 80;
constexpr int S_ = 128;
constexpr int T_ = 512;
constexpr int NC = N_ * C_;
constexpr int WPB  = 4;
constexpr int ROWW = 96;          // floats per ring row (row data = 80)
constexpr int RING = 32;          // rows in ring (8 groups)
constexpr int WSLOT = ROWW * RING;

__device__ __forceinline__ void cp16(unsigned int dst, const float* src) {
    asm volatile("cp.async.ca.shared.global [%0], [%1], 16;" :: "r"(dst), "l"(src));
}
__device__ __forceinline__ void cpcommit() { asm volatile("cp.async.commit_group;"); }
__device__ __forceinline__ void cpwait5()  { asm volatile("cp.async.wait_group 5;" ::: "memory"); }
__device__ __forceinline__ void cpwait6()  { asm volatile("cp.async.wait_group 6;" ::: "memory"); }

__global__ __launch_bounds__(WPB * 32)
void ctc_kernel(const float* __restrict__ lp, const int* __restrict__ tgt,
                const int* __restrict__ ilen, const int* __restrict__ tlen,
                float* __restrict__ out)
{
    __shared__ __align__(16) float buf[WPB][WSLOT];
    __shared__ float aval[WPB][260];
    __shared__ int   epos[WPB][32];

    const int lane = threadIdx.x & 31;
    const int w    = threadIdx.x >> 5;
    const int n    = blockIdx.x * WPB + w;
    const int len  = ilen[n];            // [T/2, T]
    const int tl   = tlen[n];            // [S/2, S]
    const int hi   = 2 * tl;             // readout states hi, hi-1

    const int4 lab4 = *reinterpret_cast<const int4*>(tgt + n * S_ + 4 * lane);
    const int l0 = lab4.x, l1 = lab4.y, l2 = lab4.z, l3 = lab4.w;
    const int prevlab = __shfl_up_sync(0xffffffffu, l3, 1);
    const float sk0 = (lane > 0 && l0 != prevlab) ? 1.f : 0.f;
    const float sk1 = (l1 != l0) ? 1.f : 0.f;
    const float sk2 = (l2 != l1) ? 1.f : 0.f;
    const float sk3 = (l3 != l2) ? 1.f : 0.f;

    const float* gsrc = lp + (size_t)n * C_ + 4 * lane;
    const unsigned int sbase = (unsigned int)__cvta_generic_to_shared(&buf[w][0]);

    // One cp.async commit-group per 4-row group g (nominal rows 4g..4g+3,
    // source row clamped to T-1, ring slot = nominal row & 31).
    auto issue_group = [&](int g) {
        if (lane < 20) {
            const int r0 = 4 * g;
            #pragma unroll
            for (int j = 0; j < 4; ++j) {
                const int rn = r0 + j;
                cp16(sbase + ((rn & (RING - 1)) * ROWW + 4 * lane) * 4,
                     gsrc + (size_t)min(rn, T_ - 1) * NC);
            }
        }
        cpcommit();
    };

    // Prologue: groups 0..7 in flight; ensure groups 0,1 (rows 0..7) complete.
    #pragma unroll
    for (int g = 0; g < 8; ++g) issue_group(g);
    cpwait6();
    __syncwarp();

    // alpha(0) from row 0.
    float a0 = 0, a1 = 0, a2 = 0, a3 = 0, a4 = 0, a5 = 0, a6 = 0, a7 = 0, a256 = 0;
    if (lane == 0) { a0 = __expf(buf[w][0]); a1 = __expf(buf[w][l0]); }

    // Emission registers for the upcoming 4 steps (rows 1..4).
    float egb[4], eg0[4], eg1[4], eg2[4], eg3[4];
    #pragma unroll
    for (int j = 0; j < 4; ++j) {
        const float* rr = &buf[w][((1 + j) & (RING - 1)) * ROWW];
        egb[j] = __expf(rr[0]);
        eg0[j] = __expf(rr[l0]); eg1[j] = __expf(rr[l1]);
        eg2[j] = __expf(rr[l2]); eg3[j] = __expf(rr[l3]);
    }

    int   E  = 0;
    float sF = (lane == 0) ? 0.f : 1.f;    // 2^(E_prev - E); 0 on lane 0
    const int ibase = lane << 3;

    #define ASTEP(j)                                                        \
    {                                                                       \
        const float pa7 = __shfl_up_sync(0xffffffffu, a7, 1) * sF;          \
        const float n0 = (a0 + pa7) * egb[j];                               \
        const float n1 = (a1 + a0 + sk0 * pa7) * eg0[j];                    \
        const float n2 = (a2 + a1) * egb[j];                                \
        const float n3 = (a3 + a2 + sk1 * a1) * eg1[j];                     \
        const float n4 = (a4 + a3) * egb[j];                                \
        const float n5 = (a5 + a4 + sk2 * a3) * eg2[j];                     \
        const float n6 = (a6 + a5) * egb[j];                                \
        const float n7 = (a7 + a6 + sk3 * a5) * eg3[j];                     \
        a256 = (a256 + a7) * egb[j];                                        \
        a0 = n0; a1 = n1; a2 = n2; a3 = n3;                                 \
        a4 = n4; a5 = n5; a6 = n6; a7 = n7;                                 \
    }

    const int kmax = (len - 5) >> 2;       // blocks k=0..kmax, t = 4k+1..4k+4
    for (int k = 0; k <= kmax; ++k) {
        ASTEP(0); ASTEP(1); ASTEP(2); ASTEP(3);

        // Keep 8 groups in flight; guarantee groups <= k+3 complete, then
        // gather+exp emissions for block k+1 (rows 4k+5..4k+8; need <= k+2).
        issue_group(k + 8);
        cpwait5();
        __syncwarp();
        #pragma unroll
        for (int j = 0; j < 4; ++j) {
            const float* rr = &buf[w][((4 * k + 5 + j) & (RING - 1)) * ROWW];
            egb[j] = __expf(rr[0]);
            eg0[j] = __expf(rr[l0]); eg1[j] = __expf(rr[l1]);
            eg2[j] = __expf(rr[l2]); eg3[j] = __expf(rr[l3]);
        }

        // Band-zero (exact reachability at t = 4k+4) + per-lane renorm.
        {
            const int t  = 4 * k + 4;
            const int lo = hi - 1 - 2 * (len - 1 - t);
            const int il = lo - ibase;
            const int ih = hi - ibase;
            a0   = (0 >= il && 0 <= ih) ? a0   : 0.f;
            a1   = (1 >= il && 1 <= ih) ? a1   : 0.f;
            a2   = (2 >= il && 2 <= ih) ? a2   : 0.f;
            a3   = (3 >= il && 3 <= ih) ? a3   : 0.f;
            a4   = (4 >= il && 4 <= ih) ? a4   : 0.f;
            a5   = (5 >= il && 5 <= ih) ? a5   : 0.f;
            a6   = (6 >= il && 6 <= ih) ? a6   : 0.f;
            a7   = (7 >= il && 7 <= ih) ? a7   : 0.f;
            a256 = (8 >= il && 8 <= ih) ? a256 : 0.f;

            float m = fmaxf(fmaxf(fmaxf(a0, a1), fmaxf(a2, a3)),
                            fmaxf(fmaxf(a4, a5), fmaxf(a6, a7)));
            m = fmaxf(m, a256);
            const bool nz = (m > 0.f);
            if (nz) {
                const int eb = (__float_as_int(m) >> 23) - 127;
                const float sc = __int_as_float((127 - eb) << 23);  // 2^-eb
                E += eb;
                a0 *= sc; a1 *= sc; a2 *= sc; a3 *= sc;
                a4 *= sc; a5 *= sc; a6 *= sc; a7 *= sc; a256 *= sc;
            }
            const int Eprev = __shfl_up_sync(0xffffffffu, E, 1);
            if (!nz) E = Eprev;
            int dE = Eprev - E;
            dE = max(-126, min(126, dE));
            sF = (lane == 0) ? 0.f : __int_as_float((127 + dE) << 23);
        }
    }

    // Tail: t = 4*(kmax+1)+1 .. len-1 (0..3 steps) using prefetched egs.
    {
        const int t0 = 4 * (kmax + 1) + 1;
        if (t0 + 0 < len) ASTEP(0);
        if (t0 + 1 < len) ASTEP(1);
        if (t0 + 2 < len) ASTEP(2);
    }
    #undef ASTEP

    // Readout: alpha_true[s] = aval[s] * 2^E(lane(s)).
    aval[w][ibase + 0] = a0; aval[w][ibase + 1] = a1;
    aval[w][ibase + 2] = a2; aval[w][ibase + 3] = a3;
    aval[w][ibase + 4] = a4; aval[w][ibase + 5] = a5;
    aval[w][ibase + 6] = a6; aval[w][ibase + 7] = a7;
    epos[w][lane] = E;
    if (lane == 31) aval[w][256] = a256;
    __syncwarp();
    if (lane == 0) {
        const float v1 = aval[w][hi];
        const float v2 = aval[w][hi - 1];
        int E1 = epos[w][min(hi >> 3, 31)];
        int E2 = epos[w][(hi - 1) >> 3];
        E1 = (v1 > 0.f) ? E1 : -2000000;
        E2 = (v2 > 0.f) ? E2 : -2000000;
        const int Em = max(E1, E2);
        const double sum = ldexp((double)v1, max(E1 - Em, -1000))
                         + ldexp((double)v2, max(E2 - Em, -1000));
        const double loss = -((double)Em * 0.6931471805599453 + log(sum));
        float lf = (float)loss;
        if (!isfinite(lf) || !(lf < 1e10f)) lf = 0.f;   // zero_infinity
        out[n] = lf;
    }
}

extern "C" void kernel_launch(void* const* d_in, const int* in_sizes, int n_in,
                              void* d_out, int out_size)
{
    const float* lp   = (const float*)d_in[0];
    const int*   tgt  = (const int*)  d_in[1];
    const int*   ilen = (const int*)  d_in[2];
    const int*   tlen = (const int*)  d_in[3];
    float*       out  = (float*)      d_out;

    ctc_kernel<<<N_ / WPB, WPB * 32>>>(lp, tgt, ilen, tlen, out);
}

// round 15
// speedup vs baseline: 2.5201x; 1.0579x over previous
#include <cuda_runtime.h>
#include <cstdint>
#include <math.h>

// CTC forward loss, linear domain, one warp per batch element, per-lane
// power-of-two scaling. Lane l owns s=8l..8l+7 (+shadow s=8l+8 in a256).
// R15: emission values gathered DIRECTLY from global with LDG into a 4-set
// register pipeline (20 floats/set), issued 3 blocks ahead, exp'd 1 block
// ahead. No smem ring, no cp.async, no per-block barriers. Band-zeroing
// dropped: per-lane exponents make the single-scale-range problem local
// (adjacent-lane dE << 126 octaves), and the full recurrence is exact.

constexpr int N_ = 512;
constexpr int C_ = 80;
constexpr int S_ = 128;
constexpr int T_ = 512;
constexpr int NC = N_ * C_;
constexpr int WPB = 4;

__global__ __launch_bounds__(WPB * 32)
void ctc_kernel(const float* __restrict__ lp, const int* __restrict__ tgt,
                const int* __restrict__ ilen, const int* __restrict__ tlen,
                float* __restrict__ out)
{
    __shared__ float aval[WPB][260];
    __shared__ int   epos[WPB][32];

    const int lane = threadIdx.x & 31;
    const int w    = threadIdx.x >> 5;
    const int n    = blockIdx.x * WPB + w;
    const int len  = ilen[n];            // [T/2, T]
    const int tl   = tlen[n];            // [S/2, S]
    const int hi   = 2 * tl;             // readout states hi, hi-1

    const int4 lab4 = *reinterpret_cast<const int4*>(tgt + n * S_ + 4 * lane);
    const int l0 = lab4.x, l1 = lab4.y, l2 = lab4.z, l3 = lab4.w;
    const int prevlab = __shfl_up_sync(0xffffffffu, l3, 1);
    const float sk0 = (lane > 0 && l0 != prevlab) ? 1.f : 0.f;
    const float sk1 = (l1 != l0) ? 1.f : 0.f;
    const float sk2 = (l2 != l1) ? 1.f : 0.f;
    const float sk3 = (l3 != l2) ? 1.f : 0.f;

    const float* rp = lp + (size_t)n * C_;
    // 5 running gather pointers: blank + this lane's 4 labels.
    const float* q0 = rp;
    const float* q1 = rp + l0;
    const float* q2 = rp + l1;
    const float* q3 = rp + l2;
    const float* q4 = rp + l3;

    float buf[4][20];                    // 4 row-set register buffers
    float egb[4], eg0[4], eg1[4], eg2[4], eg3[4];

    // alpha(0): only s=0 (blank) and s=1 (first label).
    float a0 = 0, a1 = 0, a2 = 0, a3 = 0, a4 = 0, a5 = 0, a6 = 0, a7 = 0, a256 = 0;
    if (lane == 0) { a0 = __expf(__ldg(rp)); a1 = __expf(__ldg(rp + l0)); }

    // Prologue: row-sets for blocks 0,1,2 (rows 1..12) into buf[0..2].
    #pragma unroll
    for (int b = 0; b < 3; ++b)
        #pragma unroll
        for (int j = 0; j < 4; ++j) {
            const int r = 4 * b + 1 + j;
            buf[b][5*j+0] = __ldg(q0 + r * NC);
            buf[b][5*j+1] = __ldg(q1 + r * NC);
            buf[b][5*j+2] = __ldg(q2 + r * NC);
            buf[b][5*j+3] = __ldg(q3 + r * NC);
            buf[b][5*j+4] = __ldg(q4 + r * NC);
        }
    // egs for block 0 (rows 1..4).
    #pragma unroll
    for (int j = 0; j < 4; ++j) {
        egb[j] = __expf(buf[0][5*j+0]);
        eg0[j] = __expf(buf[0][5*j+1]);
        eg1[j] = __expf(buf[0][5*j+2]);
        eg2[j] = __expf(buf[0][5*j+3]);
        eg3[j] = __expf(buf[0][5*j+4]);
    }
    // First in-body issue targets rows 13..16 (block 3).
    q0 += 13 * NC; q1 += 13 * NC; q2 += 13 * NC; q3 += 13 * NC; q4 += 13 * NC;

    int   E  = 0;
    float sF = (lane == 0) ? 0.f : 1.f;  // 2^(E_prev - E); 0 on lane 0
    const int ibase = lane << 3;

    #define ASTEP(j)                                                        \
    {                                                                       \
        const float pa7 = __shfl_up_sync(0xffffffffu, a7, 1) * sF;          \
        const float n0 = (a0 + pa7) * egb[j];                               \
        const float n1 = (a1 + a0 + sk0 * pa7) * eg0[j];                    \
        const float n2 = (a2 + a1) * egb[j];                                \
        const float n3 = (a3 + a2 + sk1 * a1) * eg1[j];                     \
        const float n4 = (a4 + a3) * egb[j];                                \
        const float n5 = (a5 + a4 + sk2 * a3) * eg2[j];                     \
        const float n6 = (a6 + a5) * egb[j];                                \
        const float n7 = (a7 + a6 + sk3 * a5) * eg3[j];                     \
        a256 = (a256 + a7) * egb[j];                                        \
        a0 = n0; a1 = n1; a2 = n2; a3 = n3;                                 \
        a4 = n4; a5 = n5; a6 = n6; a7 = n7;                                 \
    }

    #define RENORM                                                          \
    {                                                                       \
        float m = fmaxf(fmaxf(fmaxf(a0, a1), fmaxf(a2, a3)),                \
                        fmaxf(fmaxf(a4, a5), fmaxf(a6, a7)));               \
        m = fmaxf(m, a256);                                                 \
        const bool nz = (m > 0.f);                                          \
        if (nz) {                                                           \
            const int eb = (__float_as_int(m) >> 23) - 127;                 \
            const float sc = __int_as_float((127 - eb) << 23);              \
            E += eb;                                                        \
            a0 *= sc; a1 *= sc; a2 *= sc; a3 *= sc;                         \
            a4 *= sc; a5 *= sc; a6 *= sc; a7 *= sc; a256 *= sc;             \
        }                                                                   \
        const int Eprev = __shfl_up_sync(0xffffffffu, E, 1);                \
        if (!nz) E = Eprev;                                                 \
        int dE = Eprev - E; dE = max(-126, min(126, dE));                   \
        sF = (lane == 0) ? 0.f : __int_as_float((127 + dE) << 23);          \
    }

    // Block body: 4 ASTEPs for block KB; issue LDG set for block KB+3 into
    // buf[(P+3)&3]; exp egs for block KB+1 from buf[(P+1)&3] (issued 2
    // blocks ago ~1000+ cyc: covers DRAM); renorm.
    #define BODY(P, GUARD, KB)                                              \
    {                                                                       \
        if (GUARD) {                                                        \
            const int tt = 4 * (KB) + 1;                                    \
            if (tt + 0 < len) ASTEP(0)                                      \
            if (tt + 1 < len) ASTEP(1)                                      \
            if (tt + 2 < len) ASTEP(2)                                      \
            if (tt + 3 < len) ASTEP(3)                                      \
        } else { ASTEP(0) ASTEP(1) ASTEP(2) ASTEP(3) }                      \
        {                                                                   \
            const int r0 = 4 * (KB) + 13;                                   \
            _Pragma("unroll")                                               \
            for (int j = 0; j < 4; ++j) if (r0 + j < T_) {                  \
                buf[((P)+3)&3][5*j+0] = __ldg(q0 + j * NC);                 \
                buf[((P)+3)&3][5*j+1] = __ldg(q1 + j * NC);                 \
                buf[((P)+3)&3][5*j+2] = __ldg(q2 + j * NC);                 \
                buf[((P)+3)&3][5*j+3] = __ldg(q3 + j * NC);                 \
                buf[((P)+3)&3][5*j+4] = __ldg(q4 + j * NC);                 \
            }                                                               \
            q0 += 4 * NC; q1 += 4 * NC; q2 += 4 * NC;                       \
            q3 += 4 * NC; q4 += 4 * NC;                                     \
        }                                                                   \
        _Pragma("unroll")                                                   \
        for (int j = 0; j < 4; ++j) {                                       \
            egb[j] = __expf(buf[((P)+1)&3][5*j+0]);                         \
            eg0[j] = __expf(buf[((P)+1)&3][5*j+1]);                         \
            eg1[j] = __expf(buf[((P)+1)&3][5*j+2]);                         \
            eg2[j] = __expf(buf[((P)+1)&3][5*j+3]);                         \
            eg3[j] = __expf(buf[((P)+1)&3][5*j+4]);                         \
        }                                                                   \
        RENORM                                                              \
    }

    const int NBfull = (len - 1) >> 2;   // number of complete 4-step blocks
    int kb = 0;
    for (; kb + 4 <= NBfull; kb += 4) {
        BODY(0, false, kb)
        BODY(1, false, kb + 1)
        BODY(2, false, kb + 2)
        BODY(3, false, kb + 3)
    }
    // Guarded tail group: blocks kb..kb+3 cover all remaining steps
    // (<= 15, since NBfull - kb <= 3 and rem <= 3). Renorm past len is
    // representation-preserving, so only ASTEPs carry guards.
    BODY(0, true, kb)
    BODY(1, true, kb + 1)
    BODY(2, true, kb + 2)
    BODY(3, true, kb + 3)

    #undef BODY
    #undef RENORM
    #undef ASTEP

    // Readout: alpha_true[s] = aval[s] * 2^E(lane(s)).
    aval[w][ibase + 0] = a0; aval[w][ibase + 1] = a1;
    aval[w][ibase + 2] = a2; aval[w][ibase + 3] = a3;
    aval[w][ibase + 4] = a4; aval[w][ibase + 5] = a5;
    aval[w][ibase + 6] = a6; aval[w][ibase + 7] = a7;
    epos[w][lane] = E;
    if (lane == 31) aval[w][256] = a256;
    __syncwarp();
    if (lane == 0) {
        const float v1 = aval[w][hi];
        const float v2 = aval[w][hi - 1];
        int E1 = epos[w][min(hi >> 3, 31)];
        int E2 = epos[w][(hi - 1) >> 3];
        E1 = (v1 > 0.f) ? E1 : -2000000;
        E2 = (v2 > 0.f) ? E2 : -2000000;
        const int Em = max(E1, E2);
        const double sum = ldexp((double)v1, max(E1 - Em, -1000))
                         + ldexp((double)v2, max(E2 - Em, -1000));
        const double loss = -((double)Em * 0.6931471805599453 + log(sum));
        float lf = (float)loss;
        if (!isfinite(lf) || !(lf < 1e10f)) lf = 0.f;   // zero_infinity
        out[n] = lf;
    }
}

extern "C" void kernel_launch(void* const* d_in, const int* in_sizes, int n_in,
                              void* d_out, int out_size)
{
    const float* lp   = (const float*)d_in[0];
    const int*   tgt  = (const int*)  d_in[1];
    const int*   ilen = (const int*)  d_in[2];
    const int*   tlen = (const int*)  d_in[3];
    float*       out  = (float*)      d_out;

    ctc_kernel<<<N_ / WPB, WPB * 32>>>(lp, tgt, ilen, tlen, out);
}